// round 1
// baseline (speedup 1.0000x reference)
#include <cuda_runtime.h>
#include <cuda_bf16.h>
#include <math.h>

// ---------------- scratch (no allocations allowed) ----------------
#define TOK 4096            // 4 * 1024
__device__ float g_q0[TOK * 192];
__device__ float g_k0[TOK * 192];
__device__ float g_v0[TOK * 192];
__device__ float g_c0[TOK * 192];
__device__ float g_q1[TOK * 66];
__device__ float g_k1[TOK * 66];
__device__ float g_v1[TOK * 66];
__device__ float g_c1[TOK * 66];

// ---------------- GEMM: C[M,N] = (A[M,K] @ W[K,N] + bias[N]) * scale ---------
// 64x64 tile, 16-deep K tiles, 16x16 threads, 4x4 register tile, float4 LDS.
__global__ __launch_bounds__(256) void gemm64(
    const float* __restrict__ A, const float* __restrict__ W,
    const float* __restrict__ bias, float* __restrict__ C,
    int M, int N, int K, float scale)
{
    __shared__ float sAT[16][64];   // [k][row]
    __shared__ float sB[16][64];    // [k][col]

    const int tx = threadIdx.x, ty = threadIdx.y;
    const int t  = ty * 16 + tx;
    const int rBase = blockIdx.y * 64;
    const int cBase = blockIdx.x * 64;

    float acc[4][4];
#pragma unroll
    for (int i = 0; i < 4; i++)
#pragma unroll
        for (int j = 0; j < 4; j++) acc[i][j] = 0.f;

    for (int k0 = 0; k0 < K; k0 += 16) {
        // load A tile (64 rows x 16 k) transposed into sAT
#pragma unroll
        for (int i = 0; i < 4; i++) {
            int idx = t + i * 256;          // 0..1023
            int kk = idx & 15;
            int r  = idx >> 4;
            int kg = k0 + kk;
            sAT[kk][r] = (kg < K) ? A[(size_t)(rBase + r) * K + kg] : 0.f;
        }
        // load B tile (16 k x 64 cols)
#pragma unroll
        for (int i = 0; i < 4; i++) {
            int idx = t + i * 256;
            int c  = idx & 63;
            int kk = idx >> 6;
            int kg = k0 + kk;
            int cg = cBase + c;
            sB[kk][c] = (kg < K && cg < N) ? W[(size_t)kg * N + cg] : 0.f;
        }
        __syncthreads();
#pragma unroll
        for (int kk = 0; kk < 16; kk++) {
            float4 a = *(const float4*)&sAT[kk][ty * 4];
            float4 b = *(const float4*)&sB[kk][tx * 4];
            float av[4] = {a.x, a.y, a.z, a.w};
            float bv[4] = {b.x, b.y, b.z, b.w};
#pragma unroll
            for (int i = 0; i < 4; i++)
#pragma unroll
                for (int j = 0; j < 4; j++)
                    acc[i][j] = fmaf(av[i], bv[j], acc[i][j]);
        }
        __syncthreads();
    }

#pragma unroll
    for (int i = 0; i < 4; i++) {
        int r = rBase + ty * 4 + i;
#pragma unroll
        for (int j = 0; j < 4; j++) {
            int c = cBase + tx * 4 + j;
            if (c < N)
                C[(size_t)r * N + c] = (acc[i][j] + bias[c]) * scale;
        }
    }
}

// ---------------- flash attention (one thread = one query row) --------------
// Q,K,V in [token, dim] layout with dim = n_heads*DPH. mask per (b, key).
// grid.x = bs * n_heads, grid.y = qlen / 128, block = 128 threads.
template <int DPH>
__global__ __launch_bounds__(128) void attn_kernel(
    const float* __restrict__ Q, const float* __restrict__ K,
    const float* __restrict__ V, const int* __restrict__ mask,
    float* __restrict__ C, int n_heads, int qlen)
{
    const int dim = n_heads * DPH;
    const int b = blockIdx.x / n_heads;
    const int h = blockIdx.x % n_heads;
    const int qi = blockIdx.y * 128 + threadIdx.x;

    __shared__ float sK[128 * DPH];
    __shared__ float sV[128 * DPH];
    __shared__ int   sM[128];

    float q[DPH];
    {
        const float* qp = Q + (size_t)(b * qlen + qi) * dim + h * DPH;
#pragma unroll
        for (int d = 0; d < DPH; d++) q[d] = qp[d];
    }

    float m = -INFINITY, l = 0.f;
    float acc[DPH];
#pragma unroll
    for (int d = 0; d < DPH; d++) acc[d] = 0.f;

    for (int k0 = 0; k0 < qlen; k0 += 128) {
        // cooperative tile load: thread i loads key row k0+i
        {
            int kk = threadIdx.x;
            const float* kp = K + (size_t)(b * qlen + k0 + kk) * dim + h * DPH;
            const float* vp = V + (size_t)(b * qlen + k0 + kk) * dim + h * DPH;
#pragma unroll
            for (int d = 0; d < DPH; d++) {
                sK[kk * DPH + d] = kp[d];
                sV[kk * DPH + d] = vp[d];
            }
            sM[kk] = mask[b * qlen + k0 + kk];
        }
        __syncthreads();

#pragma unroll 4
        for (int k = 0; k < 128; k++) {
            float dot = 0.f;
#pragma unroll
            for (int d = 0; d < DPH; d++)
                dot = fmaf(q[d], sK[k * DPH + d], dot);
            if (sM[k] == 0) dot = -3.402823466e38f;   // finfo(f32).min

            if (dot <= m) {
                float p = __expf(dot - m);
                l += p;
#pragma unroll
                for (int d = 0; d < DPH; d++)
                    acc[d] = fmaf(p, sV[k * DPH + d], acc[d]);
            } else {
                float sc = __expf(m - dot);           // rescale old state
                l = fmaf(l, sc, 1.f);                 // p(new max) = 1
#pragma unroll
                for (int d = 0; d < DPH; d++)
                    acc[d] = fmaf(acc[d], sc, sV[k * DPH + d]);
                m = dot;
            }
        }
        __syncthreads();
    }

    const float inv = 1.f / l;
    float* cp = C + (size_t)(b * qlen + qi) * dim + h * DPH;
#pragma unroll
    for (int d = 0; d < DPH; d++) cp[d] = acc[d] * inv;
}

// ---------------- launch ----------------------------------------------------
extern "C" void kernel_launch(void* const* d_in, const int* in_sizes, int n_in,
                              void* d_out, int out_size)
{
    const float* x     = (const float*)d_in[0];
    const float* y     = (const float*)d_in[1];
    const int*   mask0 = (const int*)d_in[2];
    const int*   mask1 = (const int*)d_in[3];
    const float* q0_w = (const float*)d_in[4],  *q0_b = (const float*)d_in[5];
    const float* k0_w = (const float*)d_in[6],  *k0_b = (const float*)d_in[7];
    const float* v0_w = (const float*)d_in[8],  *v0_b = (const float*)d_in[9];
    const float* o0_w = (const float*)d_in[10], *o0_b = (const float*)d_in[11];
    const float* q1_w = (const float*)d_in[12], *q1_b = (const float*)d_in[13];
    const float* k1_w = (const float*)d_in[14], *k1_b = (const float*)d_in[15];
    const float* v1_w = (const float*)d_in[16], *v1_b = (const float*)d_in[17];
    const float* o1_w = (const float*)d_in[18], *o1_b = (const float*)d_in[19];

    float* out0 = (float*)d_out;
    float* out1 = out0 + (size_t)TOK * 192;

    float *q0, *k0, *v0, *c0, *q1, *k1, *v1, *c1;
    cudaGetSymbolAddress((void**)&q0, g_q0);
    cudaGetSymbolAddress((void**)&k0, g_k0);
    cudaGetSymbolAddress((void**)&v0, g_v0);
    cudaGetSymbolAddress((void**)&c0, g_c0);
    cudaGetSymbolAddress((void**)&q1, g_q1);
    cudaGetSymbolAddress((void**)&k1, g_k1);
    cudaGetSymbolAddress((void**)&v1, g_v1);
    cudaGetSymbolAddress((void**)&c1, g_c1);

    const float s0 = 1.0f / sqrtf(12.0f);
    const float s1 = 1.0f / sqrtf(6.0f);

    dim3 blk(16, 16);
    dim3 g0(3, 64);   // N=192: 3 col tiles, M=4096: 64 row tiles
    dim3 g1(2, 64);   // N=66

    // MHA0 projections
    gemm64<<<g0, blk>>>(x, q0_w, q0_b, q0, TOK, 192, 192, s0);
    gemm64<<<g0, blk>>>(x, k0_w, k0_b, k0, TOK, 192, 192, 1.f);
    gemm64<<<g0, blk>>>(x, v0_w, v0_b, v0, TOK, 192, 192, 1.f);
    // MHA1 projections
    gemm64<<<g1, blk>>>(y, q1_w, q1_b, q1, TOK, 66, 66, s1);
    gemm64<<<g1, blk>>>(y, k1_w, k1_b, k1, TOK, 66, 66, 1.f);
    gemm64<<<g1, blk>>>(y, v1_w, v1_b, v1, TOK, 66, 66, 1.f);

    // attention
    attn_kernel<12><<<dim3(4 * 16, 8), 128>>>(q0, k0, v0, mask0, c0, 16, 1024);
    attn_kernel<6> <<<dim3(4 * 11, 8), 128>>>(q1, k1, v1, mask1, c1, 11, 1024);

    // output projections
    gemm64<<<g0, blk>>>(c0, o0_w, o0_b, out0, TOK, 192, 192, 1.f);
    gemm64<<<g1, blk>>>(c1, o1_w, o1_b, out1, TOK, 66, 66, 1.f);
}